// round 17
// baseline (speedup 1.0000x reference)
#include <cuda_runtime.h>
#include <cuda_bf16.h>
#include <cstdint>
#include <math.h>

#define BATCH 4
#define CCH   512
#define HW    4096
#define NGRP  32
#define CPG   16

// ---------------- scratch (device globals; no allocation) ----------------
__device__ float g_xn [(size_t)BATCH * CCH * HW];          // residual fp32 [b][c][i]
__device__ __nv_bfloat16 g_xnb[(size_t)BATCH * HW * CCH];  // bf16 [b][i][c]
__device__ __nv_bfloat16 g_q  [(size_t)BATCH * HW * CCH];  // bf16 [b][i][o]
__device__ __nv_bfloat16 g_k  [(size_t)BATCH * HW * CCH];  // bf16 [b][i][o]
__device__ __nv_bfloat16 g_v  [(size_t)BATCH * CCH * HW];  // bf16 [b][c][j]
__device__ __nv_bfloat16 g_p  [(size_t)BATCH * HW * HW];   // bf16 scores->probs 128MB
__device__ __nv_bfloat16 g_ao [(size_t)BATCH * HW * CCH];  // bf16 [b][i][c]
__device__ __nv_bfloat16 g_wb [(size_t)3 * CCH * CCH];     // bf16 [Wq;Wk;Wv]
__device__ __nv_bfloat16 g_wob[(size_t)CCH * CCH];         // bf16 Wo

// ---------------- helpers ----------------
__device__ __forceinline__ uint32_t smem_u32(const void* p) {
    uint32_t a;
    asm("{ .reg .u64 t; cvta.to.shared.u64 t, %1; cvt.u32.u64 %0, t; }" : "=r"(a) : "l"(p));
    return a;
}
__device__ __forceinline__ void cp_async16(uint32_t s, const void* g) {
    asm volatile("cp.async.cg.shared.global [%0], [%1], 16;" :: "r"(s), "l"(g));
}
#define CP_COMMIT() asm volatile("cp.async.commit_group;" ::: "memory")
#define CP_WAIT(N)  asm volatile("cp.async.wait_group %0;" :: "n"(N) : "memory")

__device__ __forceinline__ uint32_t pack_bf2(float lo, float hi) {
    __nv_bfloat162 h = __floats2bfloat162_rn(lo, hi);
    return *reinterpret_cast<uint32_t*>(&h);
}
__device__ __forceinline__ float2 unpack_bf2(uint32_t u) {
    __nv_bfloat162 h = *reinterpret_cast<__nv_bfloat162*>(&u);
    return __bfloat1622float2(h);
}
__device__ __forceinline__ void ldmx4(uint32_t* r, uint32_t addr) {
    asm volatile("ldmatrix.sync.aligned.m8n8.x4.shared.b16 {%0,%1,%2,%3}, [%4];"
                 : "=r"(r[0]), "=r"(r[1]), "=r"(r[2]), "=r"(r[3]) : "r"(addr));
}
__device__ __forceinline__ void mma_bf16(float* d, const uint32_t* a, const uint32_t* b) {
    asm volatile(
        "mma.sync.aligned.m16n8k16.row.col.f32.bf16.bf16.f32 "
        "{%0,%1,%2,%3}, {%4,%5,%6,%7}, {%8,%9}, {%0,%1,%2,%3};"
        : "+f"(d[0]), "+f"(d[1]), "+f"(d[2]), "+f"(d[3])
        : "r"(a[0]), "r"(a[1]), "r"(a[2]), "r"(a[3]), "r"(b[0]), "r"(b[1]));
}

// ---------------- weight prep (convert to bf16, identity layout) ----------------
__global__ __launch_bounds__(256) void prep_wb_kernel(const float* __restrict__ src,
                                                      __nv_bfloat16* __restrict__ dst, int n) {
    int i = blockIdx.x * 256 + threadIdx.x;
    if (i < n) dst[i] = __float2bfloat16_rn(src[i]);
}

// ---------------- GroupNorm ----------------
__global__ __launch_bounds__(256) void gn_kernel(const float* __restrict__ x,
                                                 const float* __restrict__ w,
                                                 const float* __restrict__ bias) {
    int bg = blockIdx.x;
    int b = bg / NGRP, g = bg % NGRP;
    const size_t base = ((size_t)(b * CCH + g * CPG)) * HW;
    const float4* x4 = (const float4*)(x + base);
    float4* o4 = (float4*)(g_xn + base);
    int t = threadIdx.x;
    const int N4 = (CPG * HW) / 4;

    float s = 0.f, ss = 0.f;
    for (int i = t; i < N4; i += 256) {
        float4 v = x4[i];
        s  += v.x + v.y + v.z + v.w;
        ss += v.x * v.x + v.y * v.y + v.z * v.z + v.w * v.w;
    }
    __shared__ float sh0[256], sh1[256];
    sh0[t] = s; sh1[t] = ss;
    __syncthreads();
    for (int off = 128; off; off >>= 1) {
        if (t < off) { sh0[t] += sh0[t + off]; sh1[t] += sh1[t + off]; }
        __syncthreads();
    }
    const float inv = 1.f / (float)(CPG * HW);
    float mean = sh0[0] * inv;
    float var  = sh1[0] * inv - mean * mean;
    float rstd = rsqrtf(var + 1e-5f);

    for (int i = t; i < N4; i += 256) {
        int c = g * CPG + ((i * 4) >> 12);
        float sw = w[c] * rstd;
        float sb = bias[c] - mean * sw;
        float4 v = x4[i];
        float4 o;
        o.x = v.x * sw + sb; o.y = v.y * sw + sb;
        o.z = v.z * sw + sb; o.w = v.w * sw + sb;
        o4[i] = o;
    }
}

// ---------------- transpose -> xnb (bf16), identity cols ----------------
__global__ __launch_bounds__(256) void tr_kernel() {
    __shared__ float tile[32][33];
    int b = blockIdx.z;
    const float* in = g_xn + (size_t)b * CCH * HW;
    __nv_bfloat16* ob = g_xnb + (size_t)b * CCH * HW;
    int i0 = blockIdx.x * 32;
    int c0 = blockIdx.y * 32;
    int tx = threadIdx.x & 31, ty = threadIdx.x >> 5;
#pragma unroll
    for (int j = 0; j < 32; j += 8)
        tile[ty + j][tx] = in[(size_t)(c0 + ty + j) * HW + i0 + tx];
    __syncthreads();
    const int c = c0 + tx;
#pragma unroll
    for (int j = 0; j < 32; j += 8)
        ob[(size_t)(i0 + ty + j) * CCH + c] = __float2bfloat16_rn(tile[tx][ty + j]);
}

// ---------------- bf16 warp-MMA GEMM via ldmatrix (ALL GEMMs) ----------------
// D[m,n] = alpha * sum_k A[m,k]*B[n,k] (+ epilogue). Tile 128x128, K-slab 64,
// 8 warps (4m x 2n), warp 32x64. 3-stage cp.async pipeline, ONE sync per slab.
// EPI: 0 = alpha only
//      1 = +bias[m]
//      2 = +bias[n], split bf16 output: n<512 -> Cv, n>=512 -> C2v (fused QK)
//      3 = +bias[m] + resid[m,n] (fp32 out)
// OUTBF: 1 = bf16 packed output, 0 = fp32 output
#define LDPB 36                          // u32 pitch: 32 data + 4 pad (144B, odd*16 mod 128)
#define TILEB_BYTES (128 * LDPB * 4)     // 18432
#define NSTAGE 3
#define MMB_SMEM (2 * NSTAGE * TILEB_BYTES)   // 110592

template<int EPI, int OUTBF>
__global__ __launch_bounds__(256, 2) void mmb_kernel(
    const __nv_bfloat16* __restrict__ A, const __nv_bfloat16* __restrict__ B,
    void* __restrict__ Cv, void* __restrict__ C2v,
    int Kd, int lda, int ldb, int ldc,
    size_t sA, size_t sB, size_t sC,
    float alpha, const float* __restrict__ bias,
    const float* __restrict__ resid, size_t sR)
{
    extern __shared__ uint32_t smu[];
    const uint32_t sbase = smem_u32(smu);

    const int t = threadIdx.x;
    const int lane = t & 31, wid = t >> 5;
    const int gid = lane >> 2, qid = lane & 3;
    const int wm = (wid & 3) * 32, wn = (wid >> 2) * 64;

    const int bz = blockIdx.z;
    const __nv_bfloat16* Ab = A + (size_t)bz * sA;
    const __nv_bfloat16* Bb = B + (size_t)bz * sB;
    const int m0 = blockIdx.y * 128;
    const int n0 = blockIdx.x * 128;

    // loader: thread -> row t>>1, half (t&1): 4 contiguous 16B chunks
    const int lrow = t >> 1;
    const int lhf  = t & 1;

    const int a_row  = wm + (lane & 15);
    const int a_uadd = (lane >> 4) << 2;            // u32 offset
    const int b_row  = wn + ((lane & 16) >> 1) + (lane & 7);
    const int b_uadd = (lane & 8) ? 4 : 0;

    float acc[2][8][4];
#pragma unroll
    for (int mi = 0; mi < 2; mi++)
#pragma unroll
        for (int ni = 0; ni < 8; ni++)
#pragma unroll
            for (int j = 0; j < 4; j++) acc[mi][ni][j] = 0.f;

    const int nslab = Kd >> 6;
    const uint32_t ld_off = (uint32_t)((lrow * LDPB + lhf * 16) * 4);   // bytes

    // prologue: issue slabs 0 and 1 (stages 0, 1)
#pragma unroll
    for (int s = 0; s < 2; s++) {
        const __nv_bfloat16* ga = Ab + (size_t)(m0 + lrow) * lda + (s << 6) + lhf * 32;
        const __nv_bfloat16* gb = Bb + (size_t)(n0 + lrow) * ldb + (s << 6) + lhf * 32;
        uint32_t da = sbase + (uint32_t)s * TILEB_BYTES + ld_off;
        uint32_t db = sbase + (uint32_t)(NSTAGE + s) * TILEB_BYTES + ld_off;
#pragma unroll
        for (int i = 0; i < 4; i++) {
            cp_async16(da + i * 16u, ga + i * 8);
            cp_async16(db + i * 16u, gb + i * 8);
        }
        CP_COMMIT();
    }

    int stg = 0;          // stage of slab s
    int nstg = 2;         // stage for slab s+2
    for (int s = 0; s < nslab; s++) {
        CP_WAIT(1);          // slab s's group complete (only s+1 may remain)
        __syncthreads();     // all warps done computing slab s-1 -> stage nstg free

        if (s + 2 < nslab) {
            int k0 = (s + 2) << 6;
            const __nv_bfloat16* ga = Ab + (size_t)(m0 + lrow) * lda + k0 + lhf * 32;
            const __nv_bfloat16* gb = Bb + (size_t)(n0 + lrow) * ldb + k0 + lhf * 32;
            uint32_t da = sbase + (uint32_t)nstg * TILEB_BYTES + ld_off;
            uint32_t db = sbase + (uint32_t)(NSTAGE + nstg) * TILEB_BYTES + ld_off;
#pragma unroll
            for (int i = 0; i < 4; i++) {
                cp_async16(da + i * 16u, ga + i * 8);
                cp_async16(db + i * 16u, gb + i * 8);
            }
        }
        CP_COMMIT();         // commit every iter (possibly empty) to keep group indices aligned

        const uint32_t abase = sbase + (uint32_t)stg * TILEB_BYTES;
        const uint32_t bbase = sbase + (uint32_t)(NSTAGE + stg) * TILEB_BYTES;
#pragma unroll
        for (int s2 = 0; s2 < 4; s2++) {
            const int kb = s2 * 8;
            uint32_t afr[2][4];
#pragma unroll
            for (int mi = 0; mi < 2; mi++)
                ldmx4(afr[mi], abase + (uint32_t)(((a_row + mi * 16) * LDPB + kb + a_uadd) * 4));
            uint32_t bfr[8][2];
#pragma unroll
            for (int nj = 0; nj < 4; nj++) {
                uint32_t r[4];
                ldmx4(r, bbase + (uint32_t)(((b_row + nj * 16) * LDPB + kb + b_uadd) * 4));
                bfr[2 * nj][0] = r[0]; bfr[2 * nj][1] = r[1];
                bfr[2 * nj + 1][0] = r[2]; bfr[2 * nj + 1][1] = r[3];
            }
#pragma unroll
            for (int mi = 0; mi < 2; mi++)
#pragma unroll
                for (int ni = 0; ni < 8; ni++)
                    mma_bf16(acc[mi][ni], afr[mi], bfr[ni]);
        }
        stg  = (stg  + 1 == NSTAGE) ? 0 : stg + 1;
        nstg = (nstg + 1 == NSTAGE) ? 0 : nstg + 1;
    }

    // epilogue
#pragma unroll
    for (int mi = 0; mi < 2; mi++) {
        const int r0 = m0 + wm + mi * 16 + gid;
        const int r1 = r0 + 8;
        float b0 = 0.f, b1 = 0.f;
        if (EPI == 1 || EPI == 3) { b0 = bias[r0]; b1 = bias[r1]; }
#pragma unroll
        for (int ni = 0; ni < 8; ni++) {
            const int col = n0 + wn + ni * 8 + 2 * qid;
            float o00 = acc[mi][ni][0] * alpha, o01 = acc[mi][ni][1] * alpha;
            float o10 = acc[mi][ni][2] * alpha, o11 = acc[mi][ni][3] * alpha;
            if (EPI == 1 || EPI == 3) { o00 += b0; o01 += b0; o10 += b1; o11 += b1; }
            if (EPI == 2) {
                float bn0 = bias[col], bn1 = bias[col + 1];
                o00 += bn0; o01 += bn1; o10 += bn0; o11 += bn1;
            }
            if (EPI == 2) {
                uint32_t* Cb;
                int cp;
                if (col < 512) { Cb = (uint32_t*)Cv  + (size_t)bz * (sC >> 1); cp = col >> 1; }
                else           { Cb = (uint32_t*)C2v + (size_t)bz * (sC >> 1); cp = (col - 512) >> 1; }
                Cb[(size_t)r0 * (ldc >> 1) + cp] = pack_bf2(o00, o01);
                Cb[(size_t)r1 * (ldc >> 1) + cp] = pack_bf2(o10, o11);
            } else if (OUTBF) {
                uint32_t* Cb = (uint32_t*)Cv + (size_t)bz * (sC >> 1);
                const int cp = col >> 1;
                Cb[(size_t)r0 * (ldc >> 1) + cp] = pack_bf2(o00, o01);
                Cb[(size_t)r1 * (ldc >> 1) + cp] = pack_bf2(o10, o11);
            } else {
                float* Cb = (float*)Cv + (size_t)bz * sC;
                if (EPI == 3) {
                    const float* rb = resid + (size_t)bz * sR;
                    float2 rv0 = *(const float2*)(rb + (size_t)r0 * ldc + col);
                    float2 rv1 = *(const float2*)(rb + (size_t)r1 * ldc + col);
                    o00 += rv0.x; o01 += rv0.y; o10 += rv1.x; o11 += rv1.y;
                }
                *(float2*)(Cb + (size_t)r0 * ldc + col) = make_float2(o00, o01);
                *(float2*)(Cb + (size_t)r1 * ldc + col) = make_float2(o10, o11);
            }
        }
    }
}

// ---------------- row softmax: bf16 g_p -> bf16 g_p (in place, fp32 math) ----------------
__global__ __launch_bounds__(256) void softmax_kernel() {
    uint4* row = (uint4*)(g_p + (size_t)blockIdx.x * HW);
    int t = threadIdx.x;
    uint4 u[2];
    float f[2][8];
    float mx = -1e30f;
#pragma unroll
    for (int i = 0; i < 2; i++) {
        u[i] = row[t + i * 256];
        float2 a0 = unpack_bf2(u[i].x), a1 = unpack_bf2(u[i].y);
        float2 a2 = unpack_bf2(u[i].z), a3 = unpack_bf2(u[i].w);
        f[i][0] = a0.x; f[i][1] = a0.y; f[i][2] = a1.x; f[i][3] = a1.y;
        f[i][4] = a2.x; f[i][5] = a2.y; f[i][6] = a3.x; f[i][7] = a3.y;
#pragma unroll
        for (int j = 0; j < 8; j++) mx = fmaxf(mx, f[i][j]);
    }
    __shared__ float sh[8];
#pragma unroll
    for (int o = 16; o; o >>= 1) mx = fmaxf(mx, __shfl_xor_sync(0xffffffffu, mx, o));
    if ((t & 31) == 0) sh[t >> 5] = mx;
    __syncthreads();
    mx = sh[0];
#pragma unroll
    for (int i = 1; i < 8; i++) mx = fmaxf(mx, sh[i]);

    float s = 0.f;
#pragma unroll
    for (int i = 0; i < 2; i++)
#pragma unroll
        for (int j = 0; j < 8; j++) {
            f[i][j] = __expf(f[i][j] - mx);
            s += f[i][j];
        }
#pragma unroll
    for (int o = 16; o; o >>= 1) s += __shfl_xor_sync(0xffffffffu, s, o);
    __syncthreads();
    if ((t & 31) == 0) sh[t >> 5] = s;
    __syncthreads();
    s = 0.f;
#pragma unroll
    for (int i = 0; i < 8; i++) s += sh[i];
    float inv = 1.f / s;
#pragma unroll
    for (int i = 0; i < 2; i++) {
        uint4 o;
        o.x = pack_bf2(f[i][0] * inv, f[i][1] * inv);
        o.y = pack_bf2(f[i][2] * inv, f[i][3] * inv);
        o.z = pack_bf2(f[i][4] * inv, f[i][5] * inv);
        o.w = pack_bf2(f[i][6] * inv, f[i][7] * inv);
        row[t + i * 256] = o;
    }
}

// ---------------- launch ----------------
extern "C" void kernel_launch(void* const* d_in, const int* in_sizes, int n_in,
                              void* d_out, int out_size) {
    const float* x     = (const float*)d_in[0];
    const float* gn_w  = (const float*)d_in[1];
    const float* gn_b  = (const float*)d_in[2];
    const float* qkv_w = (const float*)d_in[3];
    const float* qkv_b = (const float*)d_in[4];
    const float* out_w = (const float*)d_in[5];
    const float* out_b = (const float*)d_in[6];
    float* out = (float*)d_out;

    float *xn;
    __nv_bfloat16 *xnb, *q, *k, *v, *p, *ao, *wb, *wob;
    cudaGetSymbolAddress((void**)&xn,  g_xn);
    cudaGetSymbolAddress((void**)&xnb, g_xnb);
    cudaGetSymbolAddress((void**)&q,   g_q);
    cudaGetSymbolAddress((void**)&k,   g_k);
    cudaGetSymbolAddress((void**)&v,   g_v);
    cudaGetSymbolAddress((void**)&p,   g_p);
    cudaGetSymbolAddress((void**)&ao,  g_ao);
    cudaGetSymbolAddress((void**)&wb,  g_wb);
    cudaGetSymbolAddress((void**)&wob, g_wob);

    cudaFuncSetAttribute(mmb_kernel<2,1>, cudaFuncAttributeMaxDynamicSharedMemorySize, MMB_SMEM);
    cudaFuncSetAttribute(mmb_kernel<1,1>, cudaFuncAttributeMaxDynamicSharedMemorySize, MMB_SMEM);
    cudaFuncSetAttribute(mmb_kernel<0,1>, cudaFuncAttributeMaxDynamicSharedMemorySize, MMB_SMEM);
    cudaFuncSetAttribute(mmb_kernel<3,0>, cudaFuncAttributeMaxDynamicSharedMemorySize, MMB_SMEM);

    const size_t sXN = (size_t)CCH * HW;
    const size_t sSC = (size_t)HW * HW;

    // 0) weight prep (all bf16)
    prep_wb_kernel<<<(3 * CCH * CCH + 255) / 256, 256>>>(qkv_w, wb, 3 * CCH * CCH);
    prep_wb_kernel<<<(CCH * CCH + 255) / 256, 256>>>(out_w, wob, CCH * CCH);

    // 1) GroupNorm
    gn_kernel<<<BATCH * NGRP, 256>>>(x, gn_w, gn_b);
    // 2) transpose -> xnb (bf16)
    tr_kernel<<<dim3(HW / 32, CCH / 32, BATCH), 256>>>();

    // 3) fused Q,K projection: N=1024 over [Wq;Wk], bias[n], split bf16 out
    mmb_kernel<2,1><<<dim3(1024 / 128, HW / 128, BATCH), 256, MMB_SMEM>>>(
        xnb, wb, q, k, CCH, CCH, CCH, CCH, sXN, 0, sXN, 1.f, qkv_b, nullptr, 0);

    // 4) V[c,j] = Wv[c,:] . xn[:,j] + bv
    mmb_kernel<1,1><<<dim3(HW / 128, CCH / 128, BATCH), 256, MMB_SMEM>>>(
        wb + (size_t)2 * CCH * CCH, xnb, v, nullptr, CCH, CCH, CCH, HW, 0, sXN, sXN,
        1.f, qkv_b + 2 * CCH, nullptr, 0);

    // 5) scores[i,j] = scale * Q[i,:].K[j,:]  (bf16 MMA, bf16 out directly to g_p)
    mmb_kernel<0,1><<<dim3(HW / 128, HW / 128, BATCH), 256, MMB_SMEM>>>(
        q, k, p, nullptr, CCH, CCH, CCH, HW, sXN, sXN, sSC,
        0.044194173824159216f, nullptr, nullptr, 0);

    // 6) softmax in-place on bf16 g_p
    softmax_kernel<<<BATCH * HW, 256>>>();

    // 7) ao[i,c] = P[i,:] . V[c,:]
    mmb_kernel<0,1><<<dim3(CCH / 128, HW / 128, BATCH), 256, MMB_SMEM>>>(
        p, v, ao, nullptr, HW, HW, HW, CCH, sSC, sXN, sXN, 1.f, nullptr, nullptr, 0);

    // 8) out[o,i] = Wo[o,:] . ao[i,:] + bo + xn[o,i]
    mmb_kernel<3,0><<<dim3(HW / 128, CCH / 128, BATCH), 256, MMB_SMEM>>>(
        wob, ao, out, nullptr, CCH, CCH, CCH, HW, 0, sXN, sXN, 1.f, out_b, xn, sXN);
}